// round 6
// baseline (speedup 1.0000x reference)
#include <cuda_runtime.h>
#include <math.h>
#include <float.h>
#include <stdint.h>

#define BATCH 2
#define NPTS  4096
#define DIM   128
#define MD    16
#define KNBR  32
#define EDIM  530              // 2*EDGE_IN
#define EDIMP 544              // padded to 17*32
#define NROWS (BATCH*NPTS)     // 8192

// ---------------- scratch (device globals; zero-initialized at load) ----------------
__device__ float g_G [NROWS*EDIMP];   // padded cols stay zero (never written)
__device__ float g_H [NROWS*EDIMP];
__device__ float g_mi[NROWS*MD];
__device__ float g_Hn[NROWS*(2*DIM)];
__device__ float g_knn_dist[NROWS*KNBR];
__device__ int   g_knn_idx [NROWS*KNBR];

// fast SiLU: MUFU.EX2 + MUFU.RCP, rel err ~1e-6 (threshold is 1e-3)
__device__ __forceinline__ float silu_f(float x){
    return __fdividef(x, 1.0f + __expf(-x));
}

// ---------------- kernel 1: exact KNN ----------------
__global__ __launch_bounds__(256) void knn_kernel(const float* __restrict__ coors)
{
    __shared__ unsigned long long ck[256];
    const int b = blockIdx.y, i = blockIdx.x, tid = threadIdx.x;
    const int lane = tid & 31, w = tid >> 5;
    const float* cb = coors + (size_t)b*NPTS*3;
    const float cx = cb[i*3+0], cy = cb[i*3+1], cz = cb[i*3+2];

    float dl[16];
    const int jbase = w*512 + lane;
    #pragma unroll
    for (int t = 0; t < 16; t++) {
        int j = jbase + t*32;
        float dx = cx - cb[j*3+0];
        float dy = cy - cb[j*3+1];
        float dz = cz - cb[j*3+2];
        dl[t] = __fadd_rn(__fadd_rn(__fmul_rn(dx,dx), __fmul_rn(dy,dy)), __fmul_rn(dz,dz));
    }

    for (int k = 0; k < KNBR; k++) {
        float best = FLT_MAX; int bt = 0;
        #pragma unroll
        for (int t = 0; t < 16; t++)
            if (dl[t] < best) { best = dl[t]; bt = t; }
        int bj = jbase + bt*32;
        float v = best; int jj = (best < FLT_MAX) ? bj : 0x7fffffff;
        #pragma unroll
        for (int off = 16; off > 0; off >>= 1) {
            float v2 = __shfl_xor_sync(0xffffffffu, v, off);
            int   j2 = __shfl_xor_sync(0xffffffffu, jj, off);
            if (v2 < v || (v2 == v && j2 < jj)) { v = v2; jj = j2; }
        }
        if (jj == bj) dl[bt] = FLT_MAX;
        if (lane == 0)
            ck[w*32 + k] = ((unsigned long long)__float_as_uint(v) << 32) | (unsigned int)jj;
    }
    __syncthreads();

    // bitonic sort 256 keys ascending
    #pragma unroll 1
    for (int k = 2; k <= 256; k <<= 1) {
        #pragma unroll 1
        for (int j = k >> 1; j > 0; j >>= 1) {
            int p = tid ^ j;
            if (p > tid) {
                bool asc = ((tid & k) == 0);
                unsigned long long a = ck[tid], bb = ck[p];
                if ((a > bb) == asc) { ck[tid] = bb; ck[p] = a; }
            }
            __syncthreads();
        }
    }
    if (tid < KNBR) {
        unsigned long long key = ck[tid];
        const int gi = b*NPTS + i;
        g_knn_dist[gi*KNBR + tid] = __uint_as_float((unsigned int)(key >> 32));
        g_knn_idx [gi*KNBR + tid] = (int)(unsigned int)(key & 0xffffffffu);
    }
}

// ============ fast SGEMM: 128x64 tile, BK=16, 8x4 per thread, double-buffered ============
// A: M x K row-major (lda), or concat mode: [feats(128) | g_mi(16)] with K=144.
// B: K x N row-major (natural ldb = N). C: ldc. M % 128 == 0, K % 16 == 0? (K mult of 16: 128,144,256 OK)
__global__ __launch_bounds__(256) void sgemm128(
    const float* __restrict__ A, const float* __restrict__ B,
    const float* __restrict__ bias, const float* __restrict__ resid,
    float* __restrict__ C, int M, int N, int K, int lda, int ldc,
    int act, int concat)
{
    __shared__ float As[2][16][132];
    __shared__ float Bs[2][16][68];

    const int tid = threadIdx.x;
    const int tx = tid & 15, ty = tid >> 4;
    const int rowBase = blockIdx.y * 128, colBase = blockIdx.x * 64;

    const int ar = tid >> 2;            // 0..63
    const int ak = (tid & 3) * 4;       // 0,4,8,12
    const int bk = tid >> 4;            // 0..15
    const int bn = (tid & 15) * 4;      // 0..60

    const int nTiles = K / 16;
    float acc[8][4] = {};
    float4 rA0, rA1; float rB[4];

    // ---- load tile 0 into regs ----
    {
        const int k0 = 0;
        if (concat) {
            int kk = k0 + ak;
            if (kk < DIM) {
                rA0 = *(const float4*)&A[(size_t)(rowBase + ar)*DIM + kk];
                rA1 = *(const float4*)&A[(size_t)(rowBase + ar + 64)*DIM + kk];
            } else {
                rA0 = *(const float4*)&g_mi[(size_t)(rowBase + ar)*MD + (kk - DIM)];
                rA1 = *(const float4*)&g_mi[(size_t)(rowBase + ar + 64)*MD + (kk - DIM)];
            }
        } else {
            rA0 = *(const float4*)&A[(size_t)(rowBase + ar)*lda + k0 + ak];
            rA1 = *(const float4*)&A[(size_t)(rowBase + ar + 64)*lda + k0 + ak];
        }
        #pragma unroll
        for (int j = 0; j < 4; j++) {
            int col = colBase + bn + j;
            rB[j] = (col < N) ? B[(size_t)(k0 + bk)*N + col] : 0.0f;
        }
    }
    // store tile 0
    As[0][ak+0][ar] = rA0.x; As[0][ak+1][ar] = rA0.y; As[0][ak+2][ar] = rA0.z; As[0][ak+3][ar] = rA0.w;
    As[0][ak+0][ar+64] = rA1.x; As[0][ak+1][ar+64] = rA1.y; As[0][ak+2][ar+64] = rA1.z; As[0][ak+3][ar+64] = rA1.w;
    #pragma unroll
    for (int j = 0; j < 4; j++) Bs[0][bk][bn+j] = rB[j];

    #pragma unroll 1
    for (int t = 0; t < nTiles; t++) {
        __syncthreads();
        const int buf = t & 1;
        // prefetch next tile into regs
        if (t + 1 < nTiles) {
            const int k0 = (t + 1) * 16;
            if (concat) {
                int kk = k0 + ak;
                if (kk < DIM) {
                    rA0 = *(const float4*)&A[(size_t)(rowBase + ar)*DIM + kk];
                    rA1 = *(const float4*)&A[(size_t)(rowBase + ar + 64)*DIM + kk];
                } else {
                    rA0 = *(const float4*)&g_mi[(size_t)(rowBase + ar)*MD + (kk - DIM)];
                    rA1 = *(const float4*)&g_mi[(size_t)(rowBase + ar + 64)*MD + (kk - DIM)];
                }
            } else {
                rA0 = *(const float4*)&A[(size_t)(rowBase + ar)*lda + k0 + ak];
                rA1 = *(const float4*)&A[(size_t)(rowBase + ar + 64)*lda + k0 + ak];
            }
            #pragma unroll
            for (int j = 0; j < 4; j++) {
                int col = colBase + bn + j;
                rB[j] = (col < N) ? B[(size_t)(k0 + bk)*N + col] : 0.0f;
            }
        }
        // compute current tile
        #pragma unroll
        for (int kk = 0; kk < 16; kk++) {
            float4 a0 = *(const float4*)&As[buf][kk][ty*4];
            float4 a1 = *(const float4*)&As[buf][kk][ty*4 + 64];
            float4 b4 = *(const float4*)&Bs[buf][kk][tx*4];
            float av[8] = {a0.x,a0.y,a0.z,a0.w,a1.x,a1.y,a1.z,a1.w};
            float bv[4] = {b4.x,b4.y,b4.z,b4.w};
            #pragma unroll
            for (int i = 0; i < 8; i++)
                #pragma unroll
                for (int j = 0; j < 4; j++)
                    acc[i][j] = fmaf(av[i], bv[j], acc[i][j]);
        }
        // store next tile
        if (t + 1 < nTiles) {
            const int nb = (t + 1) & 1;
            As[nb][ak+0][ar] = rA0.x; As[nb][ak+1][ar] = rA0.y; As[nb][ak+2][ar] = rA0.z; As[nb][ak+3][ar] = rA0.w;
            As[nb][ak+0][ar+64] = rA1.x; As[nb][ak+1][ar+64] = rA1.y; As[nb][ak+2][ar+64] = rA1.z; As[nb][ak+3][ar+64] = rA1.w;
            #pragma unroll
            for (int j = 0; j < 4; j++) Bs[nb][bk][bn+j] = rB[j];
        }
    }

    // ---- epilogue ----
    #pragma unroll
    for (int i = 0; i < 8; i++) {
        int r = rowBase + ty*4 + (i & 3) + ((i >> 2) ? 64 : 0);
        #pragma unroll
        for (int j = 0; j < 4; j++) {
            int col = colBase + tx*4 + j;
            if (col < N) {
                float v = acc[i][j];
                if (bias)  v += bias[col];
                if (act)   v = silu_f(v);
                if (resid) v += resid[(size_t)r*N + col];
                C[(size_t)r*ldc + col] = v;
            }
        }
    }
}

// ---------------- edge kernel: 4 warps, 2 nodes/warp, lane = edge ----------------
#define SM_W2    0
#define SM_WF    (16*EDIMP)
#define SM_WC1   (25*EDIMP)
#define SM_BC1   (SM_WC1 + 1024)
#define SM_WC2   (SM_BC1 + 64)
#define SM_BE2   (SM_WC2 + 64)
#define SM_HS    (SM_BE2 + 16)
#define HS_PITCH 36
#define HS_WARP  (2*32*HS_PITCH)
#define SM_TOTAL_FLOATS (SM_HS + 4*HS_WARP)
#define EDGE_SMEM_BYTES (SM_TOTAL_FLOATS * 4)

__global__ __launch_bounds__(128, 2) void edge_kernel(
    const float* __restrict__ coors,
    const float* __restrict__ We2,  const float* __restrict__ be2,
    const float* __restrict__ Wc1,  const float* __restrict__ bc1,
    const float* __restrict__ Wc2,  const float* __restrict__ bc2,
    const float* __restrict__ We1,
    float* __restrict__ out_coors)
{
    extern __shared__ float sm[];
    float* sW2  = sm + SM_W2;
    float* sWf  = sm + SM_WF;
    float* sWc1 = sm + SM_WC1;
    float* sBc1 = sm + SM_BC1;
    float* sWc2 = sm + SM_WC2;
    float* sBe2 = sm + SM_BE2;

    const int tid = threadIdx.x, lane = tid & 31, w = tid >> 5;
    const int b = blockIdx.y;
    const int iA = blockIdx.x * 8 + w*2;
    const int giA = b*NPTS + iA;
    const int giB = giA + 1;

    for (int t = tid; t < 16*EDIMP; t += 128) {
        int m = t / EDIMP, x = t % EDIMP;
        sW2[t] = (x < EDIM) ? We2[x*16 + m] : 0.0f;
    }
    for (int t = tid; t < 9*EDIMP; t += 128) {
        int r = t / EDIMP, x = t % EDIMP;
        sWf[t] = (x < EDIM) ? We1[(256 + r)*EDIM + x] : 0.0f;
    }
    for (int t = tid; t < 1024; t += 128) sWc1[t] = Wc1[t];
    if (tid < 64) { sBc1[tid] = bc1[tid]; sWc2[tid] = Wc2[tid]; }
    if (tid < 16) sBe2[tid] = be2[tid];
    __syncthreads();

    const float bc2v = bc2[0];

    const int   jA = g_knn_idx [giA*KNBR + lane];
    const float dA = g_knn_dist[giA*KNBR + lane];
    const int   jB = g_knn_idx [giB*KNBR + lane];
    const float dB = g_knn_dist[giB*KNBR + lane];
    float fA[9], fB[9];
    {
        const float invs[4] = {1.0f, 0.5f, 0.25f, 0.125f};
        #pragma unroll
        for (int r = 0; r < 4; r++) {
            float sv, cv;
            sincosf(dA * invs[r], &sv, &cv); fA[r] = sv; fA[4+r] = cv;
            sincosf(dB * invs[r], &sv, &cv); fB[r] = sv; fB[4+r] = cv;
        }
        fA[8] = dA; fB[8] = dB;
    }

    const float* Hb = g_H + (size_t)b*NPTS*EDIMP;
    const float* GA = g_G + (size_t)giA*EDIMP;
    const float* GB = g_G + (size_t)giB*EDIMP;
    float* hsA = sm + SM_HS + w*HS_WARP;
    float* hsB = hsA + 32*HS_PITCH;

    float accA[16] = {}, accB[16] = {};

    const int rr = (lane >> 3);
    const int cc = (lane & 7) * 4;

    #pragma unroll 1
    for (int ch = 0; ch < 17; ch++) {
        const int c0 = ch * 32;
        __syncwarp();
        #pragma unroll
        for (int i = 0; i < 8; i++) {
            int row = i*4 + rr;
            int jrA = __shfl_sync(0xffffffffu, jA, row);
            int jrB = __shfl_sync(0xffffffffu, jB, row);
            float4 va = __ldg((const float4*)(Hb + (size_t)jrA*EDIMP + c0 + cc));
            float4 vb = __ldg((const float4*)(Hb + (size_t)jrB*EDIMP + c0 + cc));
            *(float4*)&hsA[row*HS_PITCH + cc] = va;
            *(float4*)&hsB[row*HS_PITCH + cc] = vb;
        }
        __syncwarp();
        #pragma unroll
        for (int xs = 0; xs < 8; xs++) {
            const int x = c0 + xs*4;
            float4 g4a = __ldg((const float4*)(GA + x));
            float4 g4b = __ldg((const float4*)(GB + x));
            float4 h4a = *(const float4*)&hsA[lane*HS_PITCH + xs*4];
            float4 h4b = *(const float4*)&hsB[lane*HS_PITCH + xs*4];
            float ta0 = g4a.x + h4a.x, ta1 = g4a.y + h4a.y, ta2 = g4a.z + h4a.z, ta3 = g4a.w + h4a.w;
            float tb0 = g4b.x + h4b.x, tb1 = g4b.y + h4b.y, tb2 = g4b.z + h4b.z, tb3 = g4b.w + h4b.w;
            #pragma unroll
            for (int r = 0; r < 9; r++) {
                float4 wf = *(const float4*)&sWf[r*EDIMP + x];
                ta0 = fmaf(fA[r], wf.x, ta0); ta1 = fmaf(fA[r], wf.y, ta1);
                ta2 = fmaf(fA[r], wf.z, ta2); ta3 = fmaf(fA[r], wf.w, ta3);
                tb0 = fmaf(fB[r], wf.x, tb0); tb1 = fmaf(fB[r], wf.y, tb1);
                tb2 = fmaf(fB[r], wf.z, tb2); tb3 = fmaf(fB[r], wf.w, tb3);
            }
            float sa0 = silu_f(ta0), sa1 = silu_f(ta1), sa2 = silu_f(ta2), sa3 = silu_f(ta3);
            float sb0 = silu_f(tb0), sb1 = silu_f(tb1), sb2 = silu_f(tb2), sb3 = silu_f(tb3);
            #pragma unroll
            for (int m = 0; m < 16; m++) {
                float4 wm = *(const float4*)&sW2[m*EDIMP + x];
                accA[m] = fmaf(sa0, wm.x, fmaf(sa1, wm.y, fmaf(sa2, wm.z, fmaf(sa3, wm.w, accA[m]))));
                accB[m] = fmaf(sb0, wm.x, fmaf(sb1, wm.y, fmaf(sb2, wm.z, fmaf(sb3, wm.w, accB[m]))));
            }
        }
    }

    #pragma unroll 1
    for (int nn = 0; nn < 2; nn++) {
        const int gi = nn ? giB : giA;
        const int j  = nn ? jB  : jA;
        float* acc   = nn ? accB : accA;

        float mij[16];
        #pragma unroll
        for (int m = 0; m < 16; m++) mij[m] = silu_f(acc[m] + sBe2[m]);

        #pragma unroll
        for (int m = 0; m < 16; m++) {
            float v = mij[m];
            #pragma unroll
            for (int off = 16; off > 0; off >>= 1)
                v += __shfl_xor_sync(0xffffffffu, v, off);
            if (lane == m) g_mi[(size_t)gi*MD + m] = v;
        }

        float cw = 0.0f;
        #pragma unroll 4
        for (int hh = 0; hh < 64; hh++) {
            float v = sBc1[hh];
            #pragma unroll
            for (int m = 0; m < 16; m++)
                v = fmaf(mij[m], sWc1[m*64 + hh], v);
            cw = fmaf(silu_f(v), sWc2[hh], cw);
        }
        cw += bc2v;

        const float ci0 = coors[(size_t)gi*3+0];
        const float ci1 = coors[(size_t)gi*3+1];
        const float ci2 = coors[(size_t)gi*3+2];
        const float* cj = coors + ((size_t)b*NPTS + j)*3;
        float rx = cw * (ci0 - cj[0]);
        float ry = cw * (ci1 - cj[1]);
        float rz = cw * (ci2 - cj[2]);
        #pragma unroll
        for (int off = 16; off > 0; off >>= 1) {
            rx += __shfl_xor_sync(0xffffffffu, rx, off);
            ry += __shfl_xor_sync(0xffffffffu, ry, off);
            rz += __shfl_xor_sync(0xffffffffu, rz, off);
        }
        if (lane == 0) {
            out_coors[(size_t)gi*3+0] = rx + ci0;
            out_coors[(size_t)gi*3+1] = ry + ci1;
            out_coors[(size_t)gi*3+2] = rz + ci2;
        }
    }
}

// ---------------- host launcher ----------------
extern "C" void kernel_launch(void* const* d_in, const int* in_sizes, int n_in,
                              void* d_out, int out_size)
{
    const float* feats = (const float*)d_in[0];
    const float* coors = (const float*)d_in[1];
    const float* We1   = (const float*)d_in[2];
    const float* be1   = (const float*)d_in[3];
    const float* We2   = (const float*)d_in[4];
    const float* be2   = (const float*)d_in[5];
    const float* Wc1   = (const float*)d_in[6];
    const float* bc1   = (const float*)d_in[7];
    const float* Wc2   = (const float*)d_in[8];
    const float* bc2   = (const float*)d_in[9];
    const float* Wn1   = (const float*)d_in[10];
    const float* bn1   = (const float*)d_in[11];
    const float* Wn2   = (const float*)d_in[12];
    const float* bn2   = (const float*)d_in[13];

    float* out       = (float*)d_out;
    float* out_node  = out;                              // (b, n, 128)
    float* out_coors = out + (size_t)NROWS*DIM;          // (b, n, 3)

    float *G, *H, *Hn;
    cudaGetSymbolAddress((void**)&G,  g_G);
    cudaGetSymbolAddress((void**)&H,  g_H);
    cudaGetSymbolAddress((void**)&Hn, g_Hn);

    // 1) KNN
    knn_kernel<<<dim3(NPTS, BATCH), 256>>>(coors);

    // 2) G = feats @ We1[0:128] + be1 ; H = feats @ We1[128:256]  (ldc = EDIMP)
    dim3 gGH((EDIM + 63)/64, NROWS/128);
    sgemm128<<<gGH, 256>>>(feats, We1,            be1,     nullptr, G, NROWS, EDIM, DIM, DIM, EDIMP, 0, 0);
    sgemm128<<<gGH, 256>>>(feats, We1 + 128*EDIM, nullptr, nullptr, H, NROWS, EDIM, DIM, DIM, EDIMP, 0, 0);

    // 3) edge kernel (4 warps/block, 2 nodes/warp, lane = edge)
    cudaFuncSetAttribute(edge_kernel, cudaFuncAttributeMaxDynamicSharedMemorySize, EDGE_SMEM_BYTES);
    edge_kernel<<<dim3(NPTS/8, BATCH), 128, EDGE_SMEM_BYTES>>>(
        coors, We2, be2, Wc1, bc1, Wc2, bc2, We1, out_coors);

    // 4) node MLP: layer1 fused concat [feats | m_i] (K=144), layer2 + residual
    sgemm128<<<dim3((2*DIM)/64, NROWS/128), 256>>>(feats, Wn1, bn1, nullptr, Hn,
                                                   NROWS, 2*DIM, DIM+MD, DIM, 2*DIM, 1, 1);
    sgemm128<<<dim3(DIM/64, NROWS/128), 256>>>(Hn, Wn2, bn2, feats, out_node,
                                               NROWS, DIM, 2*DIM, 2*DIM, DIM, 0, 0);
}